// round 14
// baseline (speedup 1.0000x reference)
#include <cuda_runtime.h>
#include <math.h>

#define HOPSZ 512
#define MAX_NHAR 128
#define NWPAD 4416              // >= max winsize 4410, multiple of 16
#define PH 3.4061215800872442e-19f   // 2*pi / 2^64
#define MAXF 4096

typedef unsigned long long ull;

__device__ ull  g_phiq[MAXF];
__device__ int  g_nhar[MAXF];
__device__ int  g_ws[MAXF];
__device__ int  g_cost[MAXF];
__device__ int  g_perm[MAXF];

// ---- pre-pass 1: all fp64 + per-frame cost ----
__global__ void prep_kernel(const float* __restrict__ f0g, int nframes) {
    int f = blockIdx.x * blockDim.x + threadIdx.x;
    if (f >= nframes || f >= MAXF) return;
    double f0 = (double)f0g[f];
    if (f0 < 40.0) f0 = 40.0;
    double r = 44100.0 / f0;
    int nh = (int)floor(r * 0.5);
    if (nh > MAX_NHAR) nh = MAX_NHAR;
    if (nh < 1) nh = 1;
    int ws = 2 * (int)rint(r * 2.0);          // round-half-even, matches jnp.round
    if (ws > 4410) ws = 4410;
    g_nhar[f] = nh;
    g_ws[f] = ws;
    g_phiq[f] = (ull)__double2ll_rn((f0 / 44100.0) * 18446744073709551616.0);
    int nh32 = (nh + 31) & ~31;               // warp-granular harmonic count
    g_cost[f] = nh32 * ws;
}

// ---- pre-pass 2: LPT permutation by rank-counting (descending cost) ----
__global__ void rank_kernel(int nframes) {
    int f = blockIdx.x * blockDim.x + threadIdx.x;
    if (f >= nframes) return;
    int cf = g_cost[f];
    int rank = 0;
    for (int g = 0; g < nframes; ++g) {
        int cg = g_cost[g];
        rank += (cg > cf) || (cg == cf && g < f);
    }
    g_perm[rank] = f;
}

__forceinline__ __device__ ull pk2(float lo, float hi) {
    ull r; asm("mov.b64 %0, {%1,%2};" : "=l"(r) : "f"(lo), "f"(hi)); return r;
}
__forceinline__ __device__ ull fma2(ull a, ull b, ull c) {
    ull d; asm("fma.rn.f32x2 %0, %1, %2, %3;" : "=l"(d) : "l"(a), "l"(b), "l"(c)); return d;
}
__forceinline__ __device__ ull mul2(ull a, ull b) {
    ull d; asm("mul.rn.f32x2 %0, %1, %2;" : "=l"(d) : "l"(a), "l"(b)); return d;
}
__forceinline__ __device__ float hadd2(ull v) {
    float lo, hi; asm("mov.b64 {%0,%1}, %2;" : "=f"(lo), "=f"(hi) : "l"(v)); return lo + hi;
}
__forceinline__ __device__ ull neg2(ull v) { return v ^ 0x8000000080000000ULL; }

__global__ __launch_bounds__(256, 4) void czt_main_kernel(
    const float* __restrict__ x,
    float* __restrict__ out,
    int T, int nframes)
{
    __shared__ __align__(16) float xw[NWPAD];
    __shared__ float red_r[256], red_i[256];

    const int frame = g_perm[blockIdx.x];      // LPT order: heavy frames first
    const int tid = threadIdx.x;

    const int nhar = g_nhar[frame];
    const int winsize = g_ws[frame];
    const ull phi_q = g_phiq[frame];

    // ---- phase 1: windowed frame -> smem (single-cos Blackman) ----
    const int base = frame * HOPSZ - (winsize >> 1);
    const float invn = 1.0f / (float)winsize;
    const int wsz16 = (winsize + 15) & ~15;
    for (int j = tid; j < wsz16; j += 256) {
        float v = 0.0f;
        if (j < winsize) {
            int gi = base + j;
            float xv = (gi >= 0 && gi < T) ? x[gi] : 0.0f;
            float a = 6.28318530717958647692f * ((float)j * invn);
            float c = __cosf(a);
            float w = fmaf(c, fmaf(0.16f, c, -0.5f), 0.34f);   // Blackman via 1 cos
            v = xv * w;
        }
        xw[j] = v;
    }
    __syncthreads();

    // ---- warp-uniform mapping: thread = (k = tid&127, half = tid>>7) ----
    const int k = tid & (MAX_NHAR - 1);
    const int half = tid >> 7;                 // warp-uniform
    const int wk = k & ~31;                    // warp's first harmonic (uniform)

    if (wk < nhar) {                           // whole-warp skip for dead k-ranges
        const ull om_q = phi_q * (ull)(k + 1);

        // twiddles u_d = e^{-i om d}, d=0..15: exact Q64-wrapped angles
        float ccv[16], nsv[16];
        ccv[0] = 1.0f; nsv[0] = 0.0f;
        #pragma unroll
        for (int d = 1; d < 16; ++d) {
            float a = (float)(long long)(om_q * (ull)d) * PH;
            float sn, cs; __sincosf(a, &sn, &cs);
            ccv[d] = cs; nsv[d] = -sn;
        }
        ull C0 = pk2(ccv[0], ccv[1]),  C1 = pk2(ccv[2], ccv[3]);
        ull C2 = pk2(ccv[4], ccv[5]),  C3 = pk2(ccv[6], ccv[7]);
        ull C4 = pk2(ccv[8], ccv[9]),  C5 = pk2(ccv[10], ccv[11]);
        ull C6 = pk2(ccv[12], ccv[13]), C7 = pk2(ccv[14], ccv[15]);
        ull S0 = pk2(nsv[0], nsv[1]),  S1 = pk2(nsv[2], nsv[3]);
        ull S2 = pk2(nsv[4], nsv[5]),  S3 = pk2(nsv[6], nsv[7]);
        ull S4 = pk2(nsv[8], nsv[9]),  S5 = pk2(nsv[10], nsv[11]);
        ull S6 = pk2(nsv[12], nsv[13]), S7 = pk2(nsv[14], nsv[15]);

        ull W16R, W16I, NW16I;
        {
            float a = (float)(long long)(om_q * 16ull) * PH;
            float sn, cs; __sincosf(a, &sn, &cs);
            W16R = pk2(cs, cs); W16I = pk2(-sn, -sn); NW16I = pk2(sn, sn);
        }

        // uniform half-split (multiples of 16)
        const int Lc = ((wsz16 >> 1) + 15) & ~15;
        const int a0 = half ? Lc : 0;
        const int b0 = half ? wsz16 : Lc;

        ull ACCR = 0ull, ACCI = 0ull;

        for (int a2 = a0; a2 < b0; a2 += 512) {    // exact Q64 rotor resync
            ull WRp, WIp, NWIp;
            {
                float a = (float)(long long)(om_q * (ull)a2) * PH;
                float sn, cs; __sincosf(a, &sn, &cs);
                WRp = pk2(cs, cs); WIp = pk2(-sn, -sn); NWIp = pk2(sn, sn);
            }
            int bend = a2 + 512; if (bend > b0) bend = b0;
            #pragma unroll 4
            for (int j0 = a2; j0 < bend; j0 += 16) {
                ulonglong2 qa = *(const ulonglong2*)(xw + j0);
                ulonglong2 qb = *(const ulonglong2*)(xw + j0 + 4);
                ulonglong2 qc = *(const ulonglong2*)(xw + j0 + 8);
                ulonglong2 qd = *(const ulonglong2*)(xw + j0 + 12);
                // packed partials over 16 samples
                ull mr = mul2(qa.x, C0);
                mr = fma2(qa.y, C1, mr);
                mr = fma2(qb.x, C2, mr);
                mr = fma2(qb.y, C3, mr);
                mr = fma2(qc.x, C4, mr);
                mr = fma2(qc.y, C5, mr);
                mr = fma2(qd.x, C6, mr);
                mr = fma2(qd.y, C7, mr);
                ull mi = mul2(qa.x, S0);
                mi = fma2(qa.y, S1, mi);
                mi = fma2(qb.x, S2, mi);
                mi = fma2(qb.y, S3, mi);
                mi = fma2(qc.x, S4, mi);
                mi = fma2(qc.y, S5, mi);
                mi = fma2(qd.x, S6, mi);
                mi = fma2(qd.y, S7, mi);
                // fold: acc += (mr + i*mi) * (WR + i*WI)
                ACCR = fma2(mr, WRp, ACCR); ACCR = fma2(mi, NWIp, ACCR);
                ACCI = fma2(mi, WRp, ACCI); ACCI = fma2(mr, WIp, ACCI);
                // rotor advance: W *= W16 (packed)
                ull oWR = WRp, oWI = WIp;
                WRp = fma2(oWR, W16R, mul2(oWI, NW16I));
                WIp = fma2(oWR, W16I, mul2(oWI, W16R));
                NWIp = neg2(WIp);
            }
        }

        red_r[tid] = hadd2(ACCR);
        red_i[tid] = hadd2(ACCI);
    }
    __syncthreads();

    // ---- epilogue: combine halves, mask k >= nhar, scale, write ----
    if (tid < MAX_NHAR) {
        float ampl = 0.0f, phs = 0.0f;
        if (tid < nhar) {
            float rr = red_r[tid] + red_r[tid + 128];
            float ri = red_i[tid] + red_i[tid + 128];
            float scale = 2.381f / (float)((winsize >> 1) + 1);
            float yr = rr * scale, yi = ri * scale;
            ampl = sqrtf(yr * yr + yi * yi);
            phs = atan2f(yi, yr);
        }
        out[tid * nframes + frame] = ampl;
        out[(MAX_NHAR + tid) * nframes + frame] = phs;
    }
}

extern "C" void kernel_launch(void* const* d_in, const int* in_sizes, int n_in,
                              void* d_out, int out_size) {
    const float* x  = (const float*)d_in[0];
    const float* f0 = (const float*)d_in[1];
    float* out = (float*)d_out;
    int T = in_sizes[0];
    int nframes = in_sizes[1];
    prep_kernel<<<(nframes + 255) / 256, 256>>>(f0, nframes);
    rank_kernel<<<(nframes + 255) / 256, 256>>>(nframes);
    czt_main_kernel<<<nframes, 256>>>(x, out, T, nframes);
}

// round 15
// speedup vs baseline: 1.2274x; 1.2274x over previous
#include <cuda_runtime.h>
#include <math.h>

#define HOPSZ 512
#define MAX_NHAR 128
#define NWPAD 4416              // >= max winsize 4410, multiple of 16
#define PH 3.4061215800872442e-19f   // 2*pi / 2^64

typedef unsigned long long ull;

__forceinline__ __device__ ull pk2(float lo, float hi) {
    ull r; asm("mov.b64 %0, {%1,%2};" : "=l"(r) : "f"(lo), "f"(hi)); return r;
}
__forceinline__ __device__ ull fma2(ull a, ull b, ull c) {
    ull d; asm("fma.rn.f32x2 %0, %1, %2, %3;" : "=l"(d) : "l"(a), "l"(b), "l"(c)); return d;
}
__forceinline__ __device__ ull mul2(ull a, ull b) {
    ull d; asm("mul.rn.f32x2 %0, %1, %2;" : "=l"(d) : "l"(a), "l"(b)); return d;
}
__forceinline__ __device__ float hadd2(ull v) {
    float lo, hi; asm("mov.b64 {%0,%1}, %2;" : "=f"(lo), "=f"(hi) : "l"(v)); return lo + hi;
}
__forceinline__ __device__ ull neg2(ull v) { return v ^ 0x8000000080000000ULL; }

__global__ __launch_bounds__(256, 5) void czt_d8_kernel(
    const float* __restrict__ x,
    const float* __restrict__ f0g,
    float* __restrict__ out,
    int T, int nframes)
{
    __shared__ __align__(16) float xw[NWPAD];
    __shared__ float red_r[256], red_i[256];
    __shared__ ull phi_q_s;
    __shared__ int nhar_s, winsize_s;

    const int frame = blockIdx.x;
    const int tid = threadIdx.x;

    // ---- only fp64: thread 0, exact reference scalar semantics ----
    if (tid == 0) {
        double f0 = (double)f0g[frame];
        if (f0 < 40.0) f0 = 40.0;
        double r = 44100.0 / f0;
        int nh = (int)floor(r * 0.5);
        if (nh > MAX_NHAR) nh = MAX_NHAR;
        if (nh < 1) nh = 1;
        int ws = 2 * (int)rint(r * 2.0);      // round-half-even, matches jnp.round
        if (ws > 4410) ws = 4410;
        nhar_s = nh;
        winsize_s = ws;
        phi_q_s = (ull)__double2ll_rn((f0 / 44100.0) * 18446744073709551616.0);
    }
    __syncthreads();

    const int nhar = nhar_s;
    const int winsize = winsize_s;
    const ull phi_q = phi_q_s;

    // ---- phase 1: windowed frame -> smem (single-cos Blackman), pad to 16 ----
    const int base = frame * HOPSZ - (winsize >> 1);
    const float invn = 1.0f / (float)winsize;
    const int wsz16 = (winsize + 15) & ~15;
    for (int j = tid; j < wsz16; j += 256) {
        float v = 0.0f;
        if (j < winsize) {
            int gi = base + j;
            float xv = (gi >= 0 && gi < T) ? x[gi] : 0.0f;
            float a = 6.28318530717958647692f * ((float)j * invn);
            float c = __cosf(a);
            float w = fmaf(c, fmaf(0.16f, c, -0.5f), 0.34f);
            v = xv * w;
        }
        xw[j] = v;
    }
    __syncthreads();

    // ---- warp-uniform mapping: thread = (k = tid&127, half = tid>>7) ----
    const int k = tid & (MAX_NHAR - 1);
    const int half = tid >> 7;                 // warp-uniform

    const ull om_q = phi_q * (ull)(k + 1);

    // twiddles u_d = e^{-i om d}, d=0..7: exact Q64-wrapped angles
    float ccv[8], nsv[8];
    ccv[0] = 1.0f; nsv[0] = 0.0f;
    #pragma unroll
    for (int d = 1; d < 8; ++d) {
        float a = (float)(long long)(om_q * (ull)d) * PH;
        float sn, cs; __sincosf(a, &sn, &cs);
        ccv[d] = cs; nsv[d] = -sn;
    }
    ull C0 = pk2(ccv[0], ccv[1]), C1 = pk2(ccv[2], ccv[3]);
    ull C2 = pk2(ccv[4], ccv[5]), C3 = pk2(ccv[6], ccv[7]);
    ull S0 = pk2(nsv[0], nsv[1]), S1 = pk2(nsv[2], nsv[3]);
    ull S2 = pk2(nsv[4], nsv[5]), S3 = pk2(nsv[6], nsv[7]);

    // block rotor step W8 = e^{-i om 8} (exact wrapped angle)
    ull W8R, W8I, NW8I;
    {
        float a = (float)(long long)(om_q * 8ull) * PH;
        float sn, cs; __sincosf(a, &sn, &cs);
        W8R = pk2(cs, cs); W8I = pk2(-sn, -sn); NW8I = pk2(sn, sn);
    }

    // uniform half-split (multiples of 16)
    const int Lc = ((wsz16 >> 1) + 15) & ~15;
    const int a0 = half ? Lc : 0;
    const int b0 = half ? wsz16 : Lc;

    ull ACCR = 0ull, ACCI = 0ull;

    for (int a2 = a0; a2 < b0; a2 += 512) {    // exact Q64 rotor resync
        ull WRp, WIp, NWIp;
        {
            float a = (float)(long long)(om_q * (ull)a2) * PH;
            float sn, cs; __sincosf(a, &sn, &cs);
            WRp = pk2(cs, cs); WIp = pk2(-sn, -sn); NWIp = pk2(sn, sn);
        }
        int bend = a2 + 512; if (bend > b0) bend = b0;
        #pragma unroll 4
        for (int j0 = a2; j0 < bend; j0 += 8) {
            ulonglong2 qa = *(const ulonglong2*)(xw + j0);
            // packed partials over 8 samples
            ull mr = mul2(qa.x, C0);
            mr = fma2(qa.y, C1, mr);
            ull mi = mul2(qa.x, S0);
            mi = fma2(qa.y, S1, mi);
            ulonglong2 qb = *(const ulonglong2*)(xw + j0 + 4);
            mr = fma2(qb.x, C2, mr);
            mr = fma2(qb.y, C3, mr);
            mi = fma2(qb.x, S2, mi);
            mi = fma2(qb.y, S3, mi);
            // fold: acc += (mr + i*mi) * (WR + i*WI), packed-broadcast
            ACCR = fma2(mr, WRp, ACCR); ACCR = fma2(mi, NWIp, ACCR);
            ACCI = fma2(mi, WRp, ACCI); ACCI = fma2(mr, WIp, ACCI);
            // rotor advance: W *= W8 (packed)
            ull oWR = WRp, oWI = WIp;
            WRp = fma2(oWR, W8R, mul2(oWI, NW8I));
            WIp = fma2(oWR, W8I, mul2(oWI, W8R));
            NWIp = neg2(WIp);
        }
    }

    red_r[tid] = hadd2(ACCR);
    red_i[tid] = hadd2(ACCI);
    __syncthreads();

    // ---- epilogue: combine halves, mask k >= nhar, scale, write ----
    if (tid < MAX_NHAR) {
        float ampl = 0.0f, phs = 0.0f;
        if (tid < nhar) {
            float rr = red_r[tid] + red_r[tid + 128];
            float ri = red_i[tid] + red_i[tid + 128];
            float scale = 2.381f / (float)((winsize >> 1) + 1);
            float yr = rr * scale, yi = ri * scale;
            ampl = sqrtf(yr * yr + yi * yi);
            phs = atan2f(yi, yr);
        }
        out[tid * nframes + frame] = ampl;
        out[(MAX_NHAR + tid) * nframes + frame] = phs;
    }
}

extern "C" void kernel_launch(void* const* d_in, const int* in_sizes, int n_in,
                              void* d_out, int out_size) {
    const float* x  = (const float*)d_in[0];
    const float* f0 = (const float*)d_in[1];
    float* out = (float*)d_out;
    int T = in_sizes[0];
    int nframes = in_sizes[1];
    czt_d8_kernel<<<nframes, 256>>>(x, f0, out, T, nframes);
}

// round 16
// speedup vs baseline: 1.5055x; 1.2266x over previous
#include <cuda_runtime.h>
#include <math.h>

#define HOPSZ 512
#define MAX_NHAR 128
#define NWPAD 4416              // >= max winsize 4410, multiple of 16
#define PH 3.4061215800872442e-19f   // 2*pi / 2^64

typedef unsigned long long ull;

__forceinline__ __device__ ull pk2(float lo, float hi) {
    ull r; asm("mov.b64 %0, {%1,%2};" : "=l"(r) : "f"(lo), "f"(hi)); return r;
}
__forceinline__ __device__ ull fma2(ull a, ull b, ull c) {
    ull d; asm("fma.rn.f32x2 %0, %1, %2, %3;" : "=l"(d) : "l"(a), "l"(b), "l"(c)); return d;
}
__forceinline__ __device__ ull mul2(ull a, ull b) {
    ull d; asm("mul.rn.f32x2 %0, %1, %2;" : "=l"(d) : "l"(a), "l"(b)); return d;
}
__forceinline__ __device__ float hadd2(ull v) {
    float lo, hi; asm("mov.b64 {%0,%1}, %2;" : "=f"(lo), "=f"(hi) : "l"(v)); return lo + hi;
}
__forceinline__ __device__ ull neg2(ull v) { return v ^ 0x8000000080000000ULL; }

__global__ __launch_bounds__(256, 4) void czt_skip_kernel(
    const float* __restrict__ x,
    const float* __restrict__ f0g,
    float* __restrict__ out,
    int T, int nframes)
{
    __shared__ __align__(16) float xw[NWPAD];
    __shared__ float red_r[256], red_i[256];
    __shared__ ull phi_q_s;
    __shared__ int nhar_s, winsize_s;

    const int frame = blockIdx.x;
    const int tid = threadIdx.x;

    // ---- only fp64: thread 0, exact reference scalar semantics ----
    if (tid == 0) {
        double f0 = (double)f0g[frame];
        if (f0 < 40.0) f0 = 40.0;
        double r = 44100.0 / f0;
        int nh = (int)floor(r * 0.5);
        if (nh > MAX_NHAR) nh = MAX_NHAR;
        if (nh < 1) nh = 1;
        int ws = 2 * (int)rint(r * 2.0);      // round-half-even, matches jnp.round
        if (ws > 4410) ws = 4410;
        nhar_s = nh;
        winsize_s = ws;
        phi_q_s = (ull)__double2ll_rn((f0 / 44100.0) * 18446744073709551616.0);
    }
    __syncthreads();

    const int nhar = nhar_s;
    const int winsize = winsize_s;
    const ull phi_q = phi_q_s;

    // ---- phase 1: windowed frame -> smem (single-cos Blackman), pad to 16 ----
    const int base = frame * HOPSZ - (winsize >> 1);
    const float invn = 1.0f / (float)winsize;
    const int wsz16 = (winsize + 15) & ~15;
    for (int j = tid; j < wsz16; j += 256) {
        float v = 0.0f;
        if (j < winsize) {
            int gi = base + j;
            float xv = (gi >= 0 && gi < T) ? x[gi] : 0.0f;
            float a = 6.28318530717958647692f * ((float)j * invn);
            float c = __cosf(a);
            float w = fmaf(c, fmaf(0.16f, c, -0.5f), 0.34f);
            v = xv * w;
        }
        xw[j] = v;
    }
    __syncthreads();

    // ---- warp-uniform mapping: thread = (k = tid&127, half = tid>>7) ----
    const int k = tid & (MAX_NHAR - 1);
    const int half = tid >> 7;                 // warp-uniform
    const int wk = k & ~31;                    // warp's first harmonic (uniform)

    if (wk < nhar) {                           // whole-warp skip of dead k-ranges
        const ull om_q = phi_q * (ull)(k + 1);

        // twiddles u_d = e^{-i om d}, d=0..15: exact Q64-wrapped angles
        float ccv[16], nsv[16];
        ccv[0] = 1.0f; nsv[0] = 0.0f;
        #pragma unroll
        for (int d = 1; d < 16; ++d) {
            float a = (float)(long long)(om_q * (ull)d) * PH;
            float sn, cs; __sincosf(a, &sn, &cs);
            ccv[d] = cs; nsv[d] = -sn;
        }
        ull C0 = pk2(ccv[0], ccv[1]),  C1 = pk2(ccv[2], ccv[3]);
        ull C2 = pk2(ccv[4], ccv[5]),  C3 = pk2(ccv[6], ccv[7]);
        ull C4 = pk2(ccv[8], ccv[9]),  C5 = pk2(ccv[10], ccv[11]);
        ull C6 = pk2(ccv[12], ccv[13]), C7 = pk2(ccv[14], ccv[15]);
        ull S0 = pk2(nsv[0], nsv[1]),  S1 = pk2(nsv[2], nsv[3]);
        ull S2 = pk2(nsv[4], nsv[5]),  S3 = pk2(nsv[6], nsv[7]);
        ull S4 = pk2(nsv[8], nsv[9]),  S5 = pk2(nsv[10], nsv[11]);
        ull S6 = pk2(nsv[12], nsv[13]), S7 = pk2(nsv[14], nsv[15]);

        // block rotor step W16 = e^{-i om 16} (exact wrapped angle)
        ull W16R, W16I, NW16I;
        {
            float a = (float)(long long)(om_q * 16ull) * PH;
            float sn, cs; __sincosf(a, &sn, &cs);
            W16R = pk2(cs, cs); W16I = pk2(-sn, -sn); NW16I = pk2(sn, sn);
        }

        // uniform half-split (multiples of 16)
        const int Lc = ((wsz16 >> 1) + 15) & ~15;
        const int a0 = half ? Lc : 0;
        const int b0 = half ? wsz16 : Lc;

        ull ACCR = 0ull, ACCI = 0ull;

        for (int a2 = a0; a2 < b0; a2 += 512) {    // exact Q64 rotor resync
            ull WRp, WIp, NWIp;
            {
                float a = (float)(long long)(om_q * (ull)a2) * PH;
                float sn, cs; __sincosf(a, &sn, &cs);
                WRp = pk2(cs, cs); WIp = pk2(-sn, -sn); NWIp = pk2(sn, sn);
            }
            int bend = a2 + 512; if (bend > b0) bend = b0;
            #pragma unroll 4
            for (int j0 = a2; j0 < bend; j0 += 16) {
                ulonglong2 qa = *(const ulonglong2*)(xw + j0);
                ulonglong2 qb = *(const ulonglong2*)(xw + j0 + 4);
                ulonglong2 qc = *(const ulonglong2*)(xw + j0 + 8);
                ulonglong2 qd = *(const ulonglong2*)(xw + j0 + 12);
                // packed partials over 16 samples
                ull mr = mul2(qa.x, C0);
                mr = fma2(qa.y, C1, mr);
                mr = fma2(qb.x, C2, mr);
                mr = fma2(qb.y, C3, mr);
                mr = fma2(qc.x, C4, mr);
                mr = fma2(qc.y, C5, mr);
                mr = fma2(qd.x, C6, mr);
                mr = fma2(qd.y, C7, mr);
                ull mi = mul2(qa.x, S0);
                mi = fma2(qa.y, S1, mi);
                mi = fma2(qb.x, S2, mi);
                mi = fma2(qb.y, S3, mi);
                mi = fma2(qc.x, S4, mi);
                mi = fma2(qc.y, S5, mi);
                mi = fma2(qd.x, S6, mi);
                mi = fma2(qd.y, S7, mi);
                // fold: acc += (mr + i*mi) * (WR + i*WI), packed-broadcast
                ACCR = fma2(mr, WRp, ACCR); ACCR = fma2(mi, NWIp, ACCR);
                ACCI = fma2(mi, WRp, ACCI); ACCI = fma2(mr, WIp, ACCI);
                // rotor advance: W *= W16 (packed)
                ull oWR = WRp, oWI = WIp;
                WRp = fma2(oWR, W16R, mul2(oWI, NW16I));
                WIp = fma2(oWR, W16I, mul2(oWI, W16R));
                NWIp = neg2(WIp);
            }
        }

        red_r[tid] = hadd2(ACCR);
        red_i[tid] = hadd2(ACCI);
    }
    __syncthreads();

    // ---- epilogue: combine halves, mask k >= nhar, scale, write ----
    // tid < nhar implies both contributing warps (halves) were active.
    if (tid < MAX_NHAR) {
        float ampl = 0.0f, phs = 0.0f;
        if (tid < nhar) {
            float rr = red_r[tid] + red_r[tid + 128];
            float ri = red_i[tid] + red_i[tid + 128];
            float scale = 2.381f / (float)((winsize >> 1) + 1);
            float yr = rr * scale, yi = ri * scale;
            ampl = sqrtf(yr * yr + yi * yi);
            phs = atan2f(yi, yr);
        }
        out[tid * nframes + frame] = ampl;
        out[(MAX_NHAR + tid) * nframes + frame] = phs;
    }
}

extern "C" void kernel_launch(void* const* d_in, const int* in_sizes, int n_in,
                              void* d_out, int out_size) {
    const float* x  = (const float*)d_in[0];
    const float* f0 = (const float*)d_in[1];
    float* out = (float*)d_out;
    int T = in_sizes[0];
    int nframes = in_sizes[1];
    czt_skip_kernel<<<nframes, 256>>>(x, f0, out, T, nframes);
}

// round 17
// speedup vs baseline: 1.5318x; 1.0174x over previous
#include <cuda_runtime.h>
#include <math.h>

#define HOPSZ 512
#define MAX_NHAR 128
#define NWPAD 4416              // >= max winsize 4410, multiple of 16
#define PH 3.4061215800872442e-19f   // 2*pi / 2^64

typedef unsigned long long ull;

__forceinline__ __device__ ull pk2(float lo, float hi) {
    ull r; asm("mov.b64 %0, {%1,%2};" : "=l"(r) : "f"(lo), "f"(hi)); return r;
}
__forceinline__ __device__ ull fma2(ull a, ull b, ull c) {
    ull d; asm("fma.rn.f32x2 %0, %1, %2, %3;" : "=l"(d) : "l"(a), "l"(b), "l"(c)); return d;
}
__forceinline__ __device__ ull mul2(ull a, ull b) {
    ull d; asm("mul.rn.f32x2 %0, %1, %2;" : "=l"(d) : "l"(a), "l"(b)); return d;
}
__forceinline__ __device__ float hadd2(ull v) {
    float lo, hi; asm("mov.b64 {%0,%1}, %2;" : "=f"(lo), "=f"(hi) : "l"(v)); return lo + hi;
}
__forceinline__ __device__ ull neg2(ull v) { return v ^ 0x8000000080000000ULL; }

__global__ __launch_bounds__(256, 4) void czt_twshare_kernel(
    const float* __restrict__ x,
    const float* __restrict__ f0g,
    float* __restrict__ out,
    int T, int nframes)
{
    __shared__ __align__(16) float xw[NWPAD];
    __shared__ float red_r[256], red_i[256];
    __shared__ float2 twid[17][MAX_NHAR];      // d=0..16 (16 = W16), per harmonic
    __shared__ ull phi_q_s;
    __shared__ int nhar_s, winsize_s;

    const int frame = blockIdx.x;
    const int tid = threadIdx.x;

    // ---- only fp64: thread 0, exact reference scalar semantics ----
    if (tid == 0) {
        double f0 = (double)f0g[frame];
        if (f0 < 40.0) f0 = 40.0;
        double r = 44100.0 / f0;
        int nh = (int)floor(r * 0.5);
        if (nh > MAX_NHAR) nh = MAX_NHAR;
        if (nh < 1) nh = 1;
        int ws = 2 * (int)rint(r * 2.0);      // round-half-even, matches jnp.round
        if (ws > 4410) ws = 4410;
        nhar_s = nh;
        winsize_s = ws;
        phi_q_s = (ull)__double2ll_rn((f0 / 44100.0) * 18446744073709551616.0);
    }
    __syncthreads();

    const int nhar = nhar_s;
    const int winsize = winsize_s;
    const ull phi_q = phi_q_s;

    const int k = tid & (MAX_NHAR - 1);
    const int half = tid >> 7;                 // warp-uniform
    const ull om_q = phi_q * (ull)(k + 1);

    // ---- twiddle setup, split across the two half-threads of each k ----
    // half 0: d = 1..8 ; half 1: d = 9..16 (d=16 is the W16 rotor step).
    // Values are the exact Q64-wrapped __sincosf of R11/R13 — bit-identical.
    {
        int dbase = half ? 9 : 1;
        #pragma unroll
        for (int i = 0; i < 8; ++i) {
            int d = dbase + i;
            float a = (float)(long long)(om_q * (ull)d) * PH;
            float sn, cs; __sincosf(a, &sn, &cs);
            twid[d][k] = make_float2(cs, -sn);
        }
    }

    // ---- phase 1: windowed frame -> smem (single-cos Blackman), pad to 16 ----
    const int base = frame * HOPSZ - (winsize >> 1);
    const float invn = 1.0f / (float)winsize;
    const int wsz16 = (winsize + 15) & ~15;
    for (int j = tid; j < wsz16; j += 256) {
        float v = 0.0f;
        if (j < winsize) {
            int gi = base + j;
            float xv = (gi >= 0 && gi < T) ? x[gi] : 0.0f;
            float a = 6.28318530717958647692f * ((float)j * invn);
            float c = __cosf(a);
            float w = fmaf(c, fmaf(0.16f, c, -0.5f), 0.34f);
            v = xv * w;
        }
        xw[j] = v;
    }
    __syncthreads();

    // ---- gather twiddles for this k (d=0 implicit: (1, 0)) ----
    float ccv[16], nsv[16];
    ccv[0] = 1.0f; nsv[0] = 0.0f;
    #pragma unroll
    for (int d = 1; d < 16; ++d) {
        float2 t = twid[d][k];
        ccv[d] = t.x; nsv[d] = t.y;
    }
    ull C0 = pk2(ccv[0], ccv[1]),  C1 = pk2(ccv[2], ccv[3]);
    ull C2 = pk2(ccv[4], ccv[5]),  C3 = pk2(ccv[6], ccv[7]);
    ull C4 = pk2(ccv[8], ccv[9]),  C5 = pk2(ccv[10], ccv[11]);
    ull C6 = pk2(ccv[12], ccv[13]), C7 = pk2(ccv[14], ccv[15]);
    ull S0 = pk2(nsv[0], nsv[1]),  S1 = pk2(nsv[2], nsv[3]);
    ull S2 = pk2(nsv[4], nsv[5]),  S3 = pk2(nsv[6], nsv[7]);
    ull S4 = pk2(nsv[8], nsv[9]),  S5 = pk2(nsv[10], nsv[11]);
    ull S6 = pk2(nsv[12], nsv[13]), S7 = pk2(nsv[14], nsv[15]);

    ull W16R, W16I, NW16I;
    {
        float2 t = twid[16][k];                // W16 = e^{-i om 16}
        W16R = pk2(t.x, t.x); W16I = pk2(t.y, t.y); NW16I = neg2(W16I);
    }

    // uniform half-split (multiples of 16)
    const int Lc = ((wsz16 >> 1) + 15) & ~15;
    const int a0 = half ? Lc : 0;
    const int b0 = half ? wsz16 : Lc;

    ull ACCR = 0ull, ACCI = 0ull;

    for (int a2 = a0; a2 < b0; a2 += 512) {    // exact Q64 rotor resync
        ull WRp, WIp, NWIp;
        {
            float a = (float)(long long)(om_q * (ull)a2) * PH;
            float sn, cs; __sincosf(a, &sn, &cs);
            WRp = pk2(cs, cs); WIp = pk2(-sn, -sn); NWIp = pk2(sn, sn);
        }
        int bend = a2 + 512; if (bend > b0) bend = b0;
        #pragma unroll 4
        for (int j0 = a2; j0 < bend; j0 += 16) {
            ulonglong2 qa = *(const ulonglong2*)(xw + j0);
            ulonglong2 qb = *(const ulonglong2*)(xw + j0 + 4);
            ulonglong2 qc = *(const ulonglong2*)(xw + j0 + 8);
            ulonglong2 qd = *(const ulonglong2*)(xw + j0 + 12);
            // packed partials over 16 samples
            ull mr = mul2(qa.x, C0);
            mr = fma2(qa.y, C1, mr);
            mr = fma2(qb.x, C2, mr);
            mr = fma2(qb.y, C3, mr);
            mr = fma2(qc.x, C4, mr);
            mr = fma2(qc.y, C5, mr);
            mr = fma2(qd.x, C6, mr);
            mr = fma2(qd.y, C7, mr);
            ull mi = mul2(qa.x, S0);
            mi = fma2(qa.y, S1, mi);
            mi = fma2(qb.x, S2, mi);
            mi = fma2(qb.y, S3, mi);
            mi = fma2(qc.x, S4, mi);
            mi = fma2(qc.y, S5, mi);
            mi = fma2(qd.x, S6, mi);
            mi = fma2(qd.y, S7, mi);
            // fold: acc += (mr + i*mi) * (WR + i*WI), packed-broadcast
            ACCR = fma2(mr, WRp, ACCR); ACCR = fma2(mi, NWIp, ACCR);
            ACCI = fma2(mi, WRp, ACCI); ACCI = fma2(mr, WIp, ACCI);
            // rotor advance: W *= W16 (packed)
            ull oWR = WRp, oWI = WIp;
            WRp = fma2(oWR, W16R, mul2(oWI, NW16I));
            WIp = fma2(oWR, W16I, mul2(oWI, W16R));
            NWIp = neg2(WIp);
        }
    }

    red_r[tid] = hadd2(ACCR);
    red_i[tid] = hadd2(ACCI);
    __syncthreads();

    // ---- epilogue: combine halves, mask k >= nhar, scale, write ----
    if (tid < MAX_NHAR) {
        float ampl = 0.0f, phs = 0.0f;
        if (tid < nhar) {
            float rr = red_r[tid] + red_r[tid + 128];
            float ri = red_i[tid] + red_i[tid + 128];
            float scale = 2.381f / (float)((winsize >> 1) + 1);
            float yr = rr * scale, yi = ri * scale;
            ampl = sqrtf(yr * yr + yi * yi);
            phs = atan2f(yi, yr);
        }
        out[tid * nframes + frame] = ampl;
        out[(MAX_NHAR + tid) * nframes + frame] = phs;
    }
}

extern "C" void kernel_launch(void* const* d_in, const int* in_sizes, int n_in,
                              void* d_out, int out_size) {
    const float* x  = (const float*)d_in[0];
    const float* f0 = (const float*)d_in[1];
    float* out = (float*)d_out;
    int T = in_sizes[0];
    int nframes = in_sizes[1];
    czt_twshare_kernel<<<nframes, 256>>>(x, f0, out, T, nframes);
}